// round 15
// baseline (speedup 1.0000x reference)
#include <cuda_runtime.h>
#include <cuda_bf16.h>
#include <cstdint>

#define NN   100000
#define EE   1600000
#define FIN  64
#define FOUT 32
#define NTILE 128
#define NCTAS ((NN + NTILE - 1) / NTILE)   // 782
#define SPMM_BLOCKS ((EE * 8) / 256)       // 50000
#define MERGE_PERIOD 65                    // every 65th block is a dense block
#define TOTAL_BLOCKS (SPMM_BLOCKS + NCTAS) // 50782

// -------- scratch (static __device__, no allocations) --------
__device__ __align__(16) float    g_deg[NN];
__device__ __align__(16) float    g_agg[NN * FOUT];
__device__ __align__(16) uint32_t g_Bhi[128 * 64];   // Theta hi, bf16x2 k-pairs, [n][kp]
__device__ __align__(16) uint32_t g_Blo[128 * 64];   // Theta lo
__device__ __align__(16) float    g_part[(size_t)NCTAS * 16384]; // partial gates, fragment layout

// ===========================================================================
// helpers
// ===========================================================================
__device__ __forceinline__ uint32_t pack_bf2(__nv_bfloat16 a, __nv_bfloat16 b) {
    __nv_bfloat162 t; t.x = a; t.y = b;
    return *(uint32_t*)&t;
}
__device__ __forceinline__ void split2(float a0, float a1, uint32_t& hi, uint32_t& lo) {
    __nv_bfloat16 h0 = __float2bfloat16(a0);
    __nv_bfloat16 h1 = __float2bfloat16(a1);
    float l0 = a0 - __bfloat162float(h0);
    float l1 = a1 - __bfloat162float(h1);
    hi = pack_bf2(h0, h1);
    lo = pack_bf2(__float2bfloat16(l0), __float2bfloat16(l1));
}
__device__ __forceinline__ void hmma(float* d, const uint32_t* a, uint32_t b0, uint32_t b1) {
    asm volatile(
        "mma.sync.aligned.m16n8k16.row.col.f32.bf16.bf16.f32 "
        "{%0,%1,%2,%3}, {%4,%5,%6,%7}, {%8,%9}, {%0,%1,%2,%3};"
        : "+f"(d[0]), "+f"(d[1]), "+f"(d[2]), "+f"(d[3])
        : "r"(a[0]), "r"(a[1]), "r"(a[2]), "r"(a[3]), "r"(b0), "r"(b1));
}
__device__ __forceinline__ float sigf(float v) {
    return __fdividef(1.0f, 1.0f + __expf(-v));
}
__device__ __forceinline__ float tanh_(float v) {
    return fmaf(2.0f, sigf(2.0f * v), -1.0f);
}
__device__ __forceinline__ void red4(float* p, float4 v) {
    asm volatile("red.global.add.v4.f32 [%0], {%1, %2, %3, %4};"
                 :: "l"(p), "f"(v.x), "f"(v.y), "f"(v.z), "f"(v.w) : "memory");
}

// ===========================================================================
// 1) prep: zero deg+agg AND pack combined weights
//    Theta[n=g*32+f][k]: k<64: W_g[k][f]; 64..95: th0_g[k-64][f];
//    96..127: -th1_g[k-96][f]  -> hi/lo bf16x2 k-pairs
// ===========================================================================
__global__ void prep_kernel(const float* __restrict__ Wi, const float* __restrict__ thi,
                            const float* __restrict__ Wf, const float* __restrict__ thf,
                            const float* __restrict__ Wc, const float* __restrict__ thc,
                            const float* __restrict__ Wo, const float* __restrict__ tho) {
    int i = blockIdx.x * blockDim.x + threadIdx.x;
    if (i < NN * FOUT / 4)
        ((float4*)g_agg)[i] = make_float4(0.f, 0.f, 0.f, 0.f);
    if (i < NN) g_deg[i] = 0.f;
    if (i < 128 * 64) {
        int n = i >> 6, kp = i & 63;
        int g = n >> 5, f = n & 31;
        const float* W  = (g == 0) ? Wi  : (g == 1) ? Wf  : (g == 2) ? Wc  : Wo;
        const float* th = (g == 0) ? thi : (g == 1) ? thf : (g == 2) ? thc : tho;
        float v[2];
        #pragma unroll
        for (int q = 0; q < 2; q++) {
            int k = kp * 2 + q;
            if (k < 64)      v[q] = W[k * 32 + f];
            else if (k < 96) v[q] = th[(k - 64) * 32 + f];
            else             v[q] = -th[1024 + (k - 96) * 32 + f];
        }
        uint32_t hi, lo;
        split2(v[0], v[1], hi, lo);
        g_Bhi[i] = hi;
        g_Blo[i] = lo;
    }
}

// ===========================================================================
// 2) deg[row] += ew
// ===========================================================================
__global__ void deg_kernel(const int* __restrict__ ei, const float* __restrict__ ew) {
    int e = blockIdx.x * blockDim.x + threadIdx.x;
    if (e < EE) atomicAdd(&g_deg[ei[e]], ew[e]);
}

// ===========================================================================
// 3) MERGED kernel: spatially mixed spmm (LSU-bound) + dense1 (tensor-bound).
//    Every MERGE_PERIOD-th block is a dense block (782 total, spread across
//    the grid so tensor work coexists with scatter work on each SM).
//    dense1: K=96 (x|h) HMMA -> partial gates to g_part (fragment layout).
//    B smem stride 52 (52%32=20): banks gID*20+tig mod 32 all distinct.
// ===========================================================================
#define B1STRIDE 52
#define SM1_TOTAL (2 * 128 * B1STRIDE * 4)      // 53248 B

__device__ __forceinline__ float2 loadXH(const float* __restrict__ x,
                                         const float* __restrict__ h,
                                         int node, int k) {
    if (node >= NN) return make_float2(0.f, 0.f);
    if (k < 64) return __ldg((const float2*)(x + (size_t)node * FIN + k));
    return __ldg((const float2*)(h + (size_t)node * FOUT + (k - 64)));
}

__device__ void dense1_body(int bid, const float* __restrict__ x,
                            const float* __restrict__ h) {
    extern __shared__ char sm[];
    uint32_t* sBhi = (uint32_t*)sm;
    uint32_t* sBlo = sBhi + 128 * B1STRIDE;

    int tid  = threadIdx.x;
    int warp = tid >> 5;
    int lane = tid & 31;
    int gID  = lane >> 2;
    int tig  = lane & 3;

    for (int i = tid; i < 128 * 48; i += 256) {
        int n = i / 48, kp = i % 48;
        sBhi[n * B1STRIDE + kp] = g_Bhi[n * 64 + kp];
        sBlo[n * B1STRIDE + kp] = g_Blo[n * 64 + kp];
    }
    __syncthreads();

    float acc[16][4];
    #pragma unroll
    for (int nt = 0; nt < 16; nt++)
        #pragma unroll
        for (int q = 0; q < 4; q++) acc[nt][q] = 0.f;

    int r0 = warp * 16 + gID;
    int n0 = bid * NTILE + r0;
    int n1 = n0 + 8;

    #pragma unroll
    for (int ks = 0; ks < 6; ks++) {
        int k0 = ks * 16 + tig * 2;
        float2 v00 = loadXH(x, h, n0, k0);
        float2 v10 = loadXH(x, h, n1, k0);
        float2 v01 = loadXH(x, h, n0, k0 + 8);
        float2 v11 = loadXH(x, h, n1, k0 + 8);
        uint32_t ah[4], al[4];
        split2(v00.x, v00.y, ah[0], al[0]);
        split2(v10.x, v10.y, ah[1], al[1]);
        split2(v01.x, v01.y, ah[2], al[2]);
        split2(v11.x, v11.y, ah[3], al[3]);

        int kc = ks * 8 + tig;
        #pragma unroll
        for (int nt = 0; nt < 16; nt++) {
            int nrow = nt * 8 + gID;
            uint32_t bh0 = sBhi[nrow * B1STRIDE + kc];
            uint32_t bh1 = sBhi[nrow * B1STRIDE + kc + 4];
            uint32_t bl0 = sBlo[nrow * B1STRIDE + kc];
            uint32_t bl1 = sBlo[nrow * B1STRIDE + kc + 4];
            hmma(acc[nt], ah, bh0, bh1);
            hmma(acc[nt], al, bh0, bh1);
            hmma(acc[nt], ah, bl0, bl1);
        }
    }

    // store partials, fragment-linear (coalesced 128B per warp per nt)
    float4* gp = (float4*)(g_part + ((size_t)(bid * 8 + warp) * 16) * 128);
    #pragma unroll
    for (int nt = 0; nt < 16; nt++)
        gp[nt * 32 + lane] = make_float4(acc[nt][0], acc[nt][1], acc[nt][2], acc[nt][3]);
}

__device__ void spmm_body(int sbid, const int* __restrict__ ei,
                          const float* __restrict__ ew, const float* __restrict__ h) {
    int t = sbid * 256 + threadIdx.x;
    int e = t >> 3;
    if (e >= EE) return;
    int sub  = t & 7;
    int lane = threadIdx.x & 31;
    int src  = lane & ~7;
    int r = 0, c = 0; float w = 0.f;
    if (sub == 0) {
        r = __ldg(ei + e);
        c = __ldg(ei + EE + e);
        float dr = g_deg[r], dc = g_deg[c];
        float ir = (dr > 0.f) ? rsqrtf(dr) : 0.f;
        float ic = (dc > 0.f) ? rsqrtf(dc) : 0.f;
        w = ir * __ldg(ew + e) * ic;
    }
    r = __shfl_sync(0xffffffffu, r, src);
    c = __shfl_sync(0xffffffffu, c, src);
    w = __shfl_sync(0xffffffffu, w, src);
    const float4 hv = *(const float4*)(h + (size_t)c * FOUT + sub * 4);
    red4(g_agg + (size_t)r * FOUT + sub * 4,
         make_float4(w * hv.x, w * hv.y, w * hv.z, w * hv.w));
}

__global__ void __launch_bounds__(256, 3) merged_kernel(
    const int* __restrict__ ei, const float* __restrict__ ew,
    const float* __restrict__ x, const float* __restrict__ h)
{
    int b = blockIdx.x;
    int d = b / MERGE_PERIOD;
    if ((b % MERGE_PERIOD) == 0 && d < NCTAS) {
        dense1_body(d, x, h);
    } else {
        // number of dense blocks with index < b
        int ndense = min(b / MERGE_PERIOD + 1, NCTAS);
        spmm_body(b - ndense, ei, ew, h);
    }
}

// ===========================================================================
// 4) dense2: K=32 (agg) HMMA + partial reload + register epilogue.
//    B smem stride 20 (20%32=20): conflict-free bank pattern.
// ===========================================================================
#define B2STRIDE 20
#define SM2_BIAS (2 * 128 * B2STRIDE * 4)               // 20480
#define SM2_WL   (SM2_BIAS + 128 * 4)
#define SM2_TOTAL (SM2_WL + 32 * 4 + 16)

__global__ void __launch_bounds__(256, 3) dense2_kernel(
    const float* __restrict__ c,
    const float* __restrict__ bi, const float* __restrict__ cbi,
    const float* __restrict__ bf_, const float* __restrict__ cbf,
    const float* __restrict__ bc, const float* __restrict__ cbc,
    const float* __restrict__ bo, const float* __restrict__ cbo,
    const float* __restrict__ Wlin, const float* __restrict__ blin,
    float* __restrict__ out)
{
    extern __shared__ char sm[];
    uint32_t* sBhi  = (uint32_t*)sm;
    uint32_t* sBlo  = sBhi + 128 * B2STRIDE;
    float*    sBias = (float*)(sm + SM2_BIAS);
    float*    sWl   = (float*)(sm + SM2_WL);

    int tid  = threadIdx.x;
    int warp = tid >> 5;
    int lane = tid & 31;
    int gID  = lane >> 2;
    int tig  = lane & 3;

    for (int i = tid; i < 128 * 16; i += 256) {
        int n = i >> 4, kp = i & 15;
        sBhi[n * B2STRIDE + kp] = g_Bhi[n * 64 + 48 + kp];
        sBlo[n * B2STRIDE + kp] = g_Blo[n * 64 + 48 + kp];
    }
    if (tid < 128) {
        int g = tid >> 5, f = tid & 31;
        const float* b  = (g == 0) ? bi  : (g == 1) ? bf_ : (g == 2) ? bc  : bo;
        const float* cb = (g == 0) ? cbi : (g == 1) ? cbf : (g == 2) ? cbc : cbo;
        sBias[tid] = b[f] + cb[f];
        if (tid < 32) sWl[tid] = Wlin[tid];
    }
    __syncthreads();

    // init acc from dense1 partials (coalesced)
    float acc[16][4];
    const float4* gp = (const float4*)(g_part + ((size_t)(blockIdx.x * 8 + warp) * 16) * 128);
    #pragma unroll
    for (int nt = 0; nt < 16; nt++) {
        float4 v = gp[nt * 32 + lane];
        acc[nt][0] = v.x; acc[nt][1] = v.y; acc[nt][2] = v.z; acc[nt][3] = v.w;
    }

    int r0 = warp * 16 + gID;
    int n0 = blockIdx.x * NTILE + r0;
    int n1 = n0 + 8;

    #pragma unroll
    for (int ks = 0; ks < 2; ks++) {
        int k0 = ks * 16 + tig * 2;    // 0..31 within agg
        float2 v00 = (n0 < NN) ? *(const float2*)(g_agg + (size_t)n0 * FOUT + k0)     : make_float2(0.f, 0.f);
        float2 v10 = (n1 < NN) ? *(const float2*)(g_agg + (size_t)n1 * FOUT + k0)     : make_float2(0.f, 0.f);
        float2 v01 = (n0 < NN) ? *(const float2*)(g_agg + (size_t)n0 * FOUT + k0 + 8) : make_float2(0.f, 0.f);
        float2 v11 = (n1 < NN) ? *(const float2*)(g_agg + (size_t)n1 * FOUT + k0 + 8) : make_float2(0.f, 0.f);
        uint32_t ah[4], al[4];
        split2(v00.x, v00.y, ah[0], al[0]);
        split2(v10.x, v10.y, ah[1], al[1]);
        split2(v01.x, v01.y, ah[2], al[2]);
        split2(v11.x, v11.y, ah[3], al[3]);

        int kc = ks * 8 + tig;
        #pragma unroll
        for (int nt = 0; nt < 16; nt++) {
            int nrow = nt * 8 + gID;
            uint32_t bh0 = sBhi[nrow * B2STRIDE + kc];
            uint32_t bh1 = sBhi[nrow * B2STRIDE + kc + 4];
            uint32_t bl0 = sBlo[nrow * B2STRIDE + kc];
            uint32_t bl1 = sBlo[nrow * B2STRIDE + kc + 4];
            hmma(acc[nt], ah, bh0, bh1);
            hmma(acc[nt], al, bh0, bh1);
            hmma(acc[nt], ah, bl0, bl1);
        }
    }

    // register-resident epilogue (lane (gID,tig): cols {8j+2tig+q})
    float p0 = 0.f, p1 = 0.f;
    #pragma unroll
    for (int j = 0; j < 4; j++) {
        #pragma unroll
        for (int q = 0; q < 2; q++) {
            int f = 8 * j + tig * 2 + q;
            float bI = sBias[f], bF = sBias[32 + f];
            float bT = sBias[64 + f], bO = sBias[96 + f];
            float wl = sWl[f];
            {
                float vI = sigf (acc[j][q]      + bI);
                float vF = sigf (acc[4 + j][q]  + bF);
                float vT = tanh_(acc[8 + j][q]  + bT);
                float vO = sigf (acc[12 + j][q] + bO);
                float cv = (n0 < NN) ? __ldg(c + (size_t)n0 * FOUT + f) : 0.f;
                float Cn = fmaf(vF, cv, vI * vT);
                float Hn = vO * tanh_(Cn);
                p0 = fmaf(fmaxf(Hn, 0.f), wl, p0);
            }
            {
                float vI = sigf (acc[j][q + 2]      + bI);
                float vF = sigf (acc[4 + j][q + 2]  + bF);
                float vT = tanh_(acc[8 + j][q + 2]  + bT);
                float vO = sigf (acc[12 + j][q + 2] + bO);
                float cv = (n1 < NN) ? __ldg(c + (size_t)n1 * FOUT + f) : 0.f;
                float Cn = fmaf(vF, cv, vI * vT);
                float Hn = vO * tanh_(Cn);
                p1 = fmaf(fmaxf(Hn, 0.f), wl, p1);
            }
        }
    }
    p0 += __shfl_xor_sync(0xffffffffu, p0, 1);
    p0 += __shfl_xor_sync(0xffffffffu, p0, 2);
    p1 += __shfl_xor_sync(0xffffffffu, p1, 1);
    p1 += __shfl_xor_sync(0xffffffffu, p1, 2);
    if (tig == 0) {
        float blin0 = __ldg(blin);
        if (n0 < NN) out[n0] = p0 + blin0;
        if (n1 < NN) out[n1] = p1 + blin0;
    }
}

// ===========================================================================
extern "C" void kernel_launch(void* const* d_in, const int* in_sizes, int n_in,
                              void* d_out, int out_size)
{
    const float* x    = (const float*)d_in[0];
    const int*   ei   = (const int*)  d_in[1];
    const float* ew   = (const float*)d_in[2];
    const float* h    = (const float*)d_in[3];
    const float* c    = (const float*)d_in[4];
    const float* Wi   = (const float*)d_in[5];
    const float* bi   = (const float*)d_in[6];
    const float* thi  = (const float*)d_in[7];
    const float* cbi  = (const float*)d_in[8];
    const float* Wf   = (const float*)d_in[9];
    const float* bf   = (const float*)d_in[10];
    const float* thf  = (const float*)d_in[11];
    const float* cbf  = (const float*)d_in[12];
    const float* Wc   = (const float*)d_in[13];
    const float* bc   = (const float*)d_in[14];
    const float* thc  = (const float*)d_in[15];
    const float* cbc  = (const float*)d_in[16];
    const float* Wo   = (const float*)d_in[17];
    const float* bo   = (const float*)d_in[18];
    const float* tho  = (const float*)d_in[19];
    const float* cbo  = (const float*)d_in[20];
    const float* Wlin = (const float*)d_in[21];
    const float* blin = (const float*)d_in[22];
    float* out = (float*)d_out;

    cudaFuncSetAttribute(merged_kernel,
                         cudaFuncAttributeMaxDynamicSharedMemorySize, SM1_TOTAL);
    cudaFuncSetAttribute(dense2_kernel,
                         cudaFuncAttributeMaxDynamicSharedMemorySize, SM2_TOTAL);

    prep_kernel<<<(NN * FOUT / 4 + 255) / 256, 256>>>(Wi, thi, Wf, thf, Wc, thc, Wo, tho);
    deg_kernel<<<(EE + 255) / 256, 256>>>(ei, ew);
    merged_kernel<<<TOTAL_BLOCKS, 256, SM1_TOTAL>>>(ei, ew, x, h);
    dense2_kernel<<<NCTAS, 256, SM2_TOTAL>>>(
        c, bi, cbi, bf, cbf, bc, cbc, bo, cbo, Wlin, blin, out);
}

// round 16
// speedup vs baseline: 1.9665x; 1.9665x over previous
#include <cuda_runtime.h>
#include <cuda_bf16.h>
#include <cstdint>

#define NN   100000
#define EE   1600000
#define FIN  64
#define FOUT 32
#define NTILE 128
#define NCTAS ((NN + NTILE - 1) / NTILE)   // 782

// -------- scratch (static __device__, no allocations) --------
__device__ __align__(16) float    g_deg[NN];
__device__ __align__(16) float    g_agg[NN * FOUT];
// paired layout: g_B*[n*64 + p], p = ks*8 + tig*2 + half  <->  kp = ks*8 + tig + 4*half
__device__ __align__(16) uint32_t g_Bhi[128 * 64];
__device__ __align__(16) uint32_t g_Blo[128 * 64];

// ===========================================================================
// helpers
// ===========================================================================
__device__ __forceinline__ void split2(float a0, float a1, uint32_t& hi, uint32_t& lo) {
    // hi = bf16x2(lower=a0, upper=a1), 1 instr
    asm("cvt.rn.bf16x2.f32 %0, %1, %2;" : "=r"(hi) : "f"(a1), "f"(a0));
    // exact f32 values of the bf16 halves via bit tricks
    float f0 = __uint_as_float(hi << 16);
    float f1 = __uint_as_float(hi & 0xffff0000u);
    float l0 = a0 - f0;
    float l1 = a1 - f1;
    asm("cvt.rn.bf16x2.f32 %0, %1, %2;" : "=r"(lo) : "f"(l1), "f"(l0));
}
__device__ __forceinline__ void hmma(float* d, const uint32_t* a, uint32_t b0, uint32_t b1) {
    asm volatile(
        "mma.sync.aligned.m16n8k16.row.col.f32.bf16.bf16.f32 "
        "{%0,%1,%2,%3}, {%4,%5,%6,%7}, {%8,%9}, {%0,%1,%2,%3};"
        : "+f"(d[0]), "+f"(d[1]), "+f"(d[2]), "+f"(d[3])
        : "r"(a[0]), "r"(a[1]), "r"(a[2]), "r"(a[3]), "r"(b0), "r"(b1));
}
__device__ __forceinline__ float sigf(float v) {
    return __fdividef(1.0f, 1.0f + __expf(-v));
}
__device__ __forceinline__ float tanh_(float v) {
    return fmaf(2.0f, sigf(2.0f * v), -1.0f);
}
__device__ __forceinline__ void red4(float* p, float4 v) {
    asm volatile("red.global.add.v4.f32 [%0], {%1, %2, %3, %4};"
                 :: "l"(p), "f"(v.x), "f"(v.y), "f"(v.z), "f"(v.w) : "memory");
}

// ===========================================================================
// 1) prep: zero deg+agg AND pack combined weights in PAIRED layout.
//    Theta[n=g*32+f][k]: k<64: W_g[k][f]; 64..95: th0_g[k-64][f];
//    96..127: -th1_g[k-96][f]
//    word position p = ks*8 + tig*2 + half holds bf16x2 of k-pair
//    kp = ks*8 + tig + 4*half (i.e. floats k=2kp, 2kp+1).
// ===========================================================================
__global__ void prep_kernel(const float* __restrict__ Wi, const float* __restrict__ thi,
                            const float* __restrict__ Wf, const float* __restrict__ thf,
                            const float* __restrict__ Wc, const float* __restrict__ thc,
                            const float* __restrict__ Wo, const float* __restrict__ tho) {
    int i = blockIdx.x * blockDim.x + threadIdx.x;
    if (i < NN * FOUT / 4)
        ((float4*)g_agg)[i] = make_float4(0.f, 0.f, 0.f, 0.f);
    if (i < NN) g_deg[i] = 0.f;
    if (i < 128 * 64) {
        int n = i >> 6, p = i & 63;
        int ks = p >> 3, tg = (p >> 1) & 3, half = p & 1;
        int kp = ks * 8 + tg + 4 * half;
        int g = n >> 5, f = n & 31;
        const float* W  = (g == 0) ? Wi  : (g == 1) ? Wf  : (g == 2) ? Wc  : Wo;
        const float* th = (g == 0) ? thi : (g == 1) ? thf : (g == 2) ? thc : tho;
        float v[2];
        #pragma unroll
        for (int q = 0; q < 2; q++) {
            int k = kp * 2 + q;
            if (k < 64)      v[q] = W[k * 32 + f];
            else if (k < 96) v[q] = th[(k - 64) * 32 + f];
            else             v[q] = -th[1024 + (k - 96) * 32 + f];
        }
        uint32_t hi, lo;
        split2(v[0], v[1], hi, lo);
        g_Bhi[i] = hi;
        g_Blo[i] = lo;
    }
}

// ===========================================================================
// 2) deg[row] += ew
// ===========================================================================
__global__ void deg_kernel(const int* __restrict__ ei, const float* __restrict__ ew) {
    int e = blockIdx.x * blockDim.x + threadIdx.x;
    if (e < EE) atomicAdd(&g_deg[ei[e]], ew[e]);
}

// ===========================================================================
// 3) scatter SpMM, vector RED + shfl broadcast; rsqrt inline (R13, 56us)
// ===========================================================================
__global__ void __launch_bounds__(256) spmm4_kernel(const int* __restrict__ ei,
                                                    const float* __restrict__ ew,
                                                    const float* __restrict__ h) {
    int t = blockIdx.x * 256 + threadIdx.x;
    int e = t >> 3;
    if (e >= EE) return;
    int sub  = t & 7;
    int lane = threadIdx.x & 31;
    int src  = lane & ~7;
    int r = 0, c = 0; float w = 0.f;
    if (sub == 0) {
        r = __ldg(ei + e);
        c = __ldg(ei + EE + e);
        float dr = g_deg[r], dc = g_deg[c];
        float ir = (dr > 0.f) ? rsqrtf(dr) : 0.f;
        float ic = (dc > 0.f) ? rsqrtf(dc) : 0.f;
        w = ir * __ldg(ew + e) * ic;
    }
    r = __shfl_sync(0xffffffffu, r, src);
    c = __shfl_sync(0xffffffffu, c, src);
    w = __shfl_sync(0xffffffffu, w, src);
    const float4 hv = *(const float4*)(h + (size_t)c * FOUT + sub * 4);
    red4(g_agg + (size_t)r * FOUT + sub * 4,
         make_float4(w * hv.x, w * hv.y, w * hv.z, w * hv.w));
}

// ===========================================================================
// 4) dense HMMA kernel (R13 monolith + LDS.64 paired B).
//    B smem stride 72 words (72%32=8): per 16-lane LDS.64 phase the banks are
//    gID*8 + tig*2 + {0,1} -> all 32 distinct -> conflict-free.
//    A direct-from-global; register-resident epilogue.
// ===========================================================================
#define BSTRIDE 72

#define SM_BHI  0
#define SM_BLO  (SM_BHI + 128 * BSTRIDE * 4)    // 36864
#define SM_BIAS (SM_BLO + 128 * BSTRIDE * 4)    // 73728
#define SM_WL   (SM_BIAS + 128 * 4)             // 74240
#define SM_TOTAL (SM_WL + 32 * 4 + 16)          // 74384 -> 3 CTAs/SM

__device__ __forceinline__ float2 loadA(const float* __restrict__ x,
                                        const float* __restrict__ h,
                                        int node, int k) {
    if (node >= NN) return make_float2(0.f, 0.f);
    if (k < 64)  return __ldg((const float2*)(x + (size_t)node * FIN + k));
    if (k < 96)  return __ldg((const float2*)(h + (size_t)node * FOUT + (k - 64)));
    return *(const float2*)(g_agg + (size_t)node * FOUT + (k - 96));
}

__global__ void __launch_bounds__(256, 3) dense_kernel(
    const float* __restrict__ x, const float* __restrict__ h,
    const float* __restrict__ c,
    const float* __restrict__ bi, const float* __restrict__ cbi,
    const float* __restrict__ bf_, const float* __restrict__ cbf,
    const float* __restrict__ bc, const float* __restrict__ cbc,
    const float* __restrict__ bo, const float* __restrict__ cbo,
    const float* __restrict__ Wlin, const float* __restrict__ blin,
    float* __restrict__ out)
{
    extern __shared__ char sm[];
    uint32_t* sBhi  = (uint32_t*)(sm + SM_BHI);
    uint32_t* sBlo  = (uint32_t*)(sm + SM_BLO);
    float*    sBias = (float*)(sm + SM_BIAS);
    float*    sWl   = (float*)(sm + SM_WL);

    int tid  = threadIdx.x;
    int warp = tid >> 5;
    int lane = tid & 31;
    int gID  = lane >> 2;      // 0..7
    int tig  = lane & 3;       // 0..3

    // ---- load B (paired layout) into strided smem ----
    for (int i = tid; i < 128 * 64; i += 256) {
        int n = i >> 6, p = i & 63;
        sBhi[n * BSTRIDE + p] = g_Bhi[i];
        sBlo[n * BSTRIDE + p] = g_Blo[i];
    }
    // ---- bias + W_lin ----
    if (tid < 128) {
        int g = tid >> 5, f = tid & 31;
        const float* b  = (g == 0) ? bi  : (g == 1) ? bf_ : (g == 2) ? bc  : bo;
        const float* cb = (g == 0) ? cbi : (g == 1) ? cbf : (g == 2) ? cbc : cbo;
        sBias[tid] = b[f] + cb[f];
        if (tid < 32) sWl[tid] = Wlin[tid];
    }
    __syncthreads();

    // ---- MMA: warp owns 16 node-rows (warp*16 + gID, +8), A from global ----
    float acc[16][4];
    #pragma unroll
    for (int nt = 0; nt < 16; nt++)
        #pragma unroll
        for (int q = 0; q < 4; q++) acc[nt][q] = 0.f;

    int r0 = warp * 16 + gID;          // node-local fragment rows
    int n0 = blockIdx.x * NTILE + r0;  // global nodes
    int n1 = n0 + 8;

    #pragma unroll
    for (int ks = 0; ks < 8; ks++) {
        int k0 = ks * 16 + tig * 2;    // element index of first pair
        float2 v00 = loadA(x, h, n0, k0);
        float2 v10 = loadA(x, h, n1, k0);
        float2 v01 = loadA(x, h, n0, k0 + 8);
        float2 v11 = loadA(x, h, n1, k0 + 8);
        uint32_t ah[4], al[4];
        split2(v00.x, v00.y, ah[0], al[0]);
        split2(v10.x, v10.y, ah[1], al[1]);
        split2(v01.x, v01.y, ah[2], al[2]);
        split2(v11.x, v11.y, ah[3], al[3]);

        int pbase = ks * 8 + tig * 2;  // paired word position
        #pragma unroll
        for (int nt = 0; nt < 16; nt++) {
            int nrow = nt * 8 + gID;
            uint2 bh = *(const uint2*)(sBhi + nrow * BSTRIDE + pbase);  // LDS.64
            uint2 bl = *(const uint2*)(sBlo + nrow * BSTRIDE + pbase);
            hmma(acc[nt], ah, bh.x, bh.y);
            hmma(acc[nt], al, bh.x, bh.y);
            hmma(acc[nt], ah, bl.x, bl.y);
        }
    }

    // ---- register-resident epilogue ----
    // lane (gID, tig) holds, for rows r0/r1, gate columns {8j + 2tig + q}:
    // I at nt=j, F at nt=4+j, C at nt=8+j, O at nt=12+j.
    float p0 = 0.f, p1 = 0.f;
    #pragma unroll
    for (int j = 0; j < 4; j++) {
        #pragma unroll
        for (int q = 0; q < 2; q++) {
            int f = 8 * j + tig * 2 + q;
            float bI = sBias[f], bF = sBias[32 + f];
            float bT = sBias[64 + f], bO = sBias[96 + f];
            float wl = sWl[f];
            {
                float vI = sigf (acc[j][q]      + bI);
                float vF = sigf (acc[4 + j][q]  + bF);
                float vT = tanh_(acc[8 + j][q]  + bT);
                float vO = sigf (acc[12 + j][q] + bO);
                float cv = (n0 < NN) ? __ldg(c + (size_t)n0 * FOUT + f) : 0.f;
                float Cn = fmaf(vF, cv, vI * vT);
                float Hn = vO * tanh_(Cn);
                p0 = fmaf(fmaxf(Hn, 0.f), wl, p0);
            }
            {
                float vI = sigf (acc[j][q + 2]      + bI);
                float vF = sigf (acc[4 + j][q + 2]  + bF);
                float vT = tanh_(acc[8 + j][q + 2]  + bT);
                float vO = sigf (acc[12 + j][q + 2] + bO);
                float cv = (n1 < NN) ? __ldg(c + (size_t)n1 * FOUT + f) : 0.f;
                float Cn = fmaf(vF, cv, vI * vT);
                float Hn = vO * tanh_(Cn);
                p1 = fmaf(fmaxf(Hn, 0.f), wl, p1);
            }
        }
    }
    p0 += __shfl_xor_sync(0xffffffffu, p0, 1);
    p0 += __shfl_xor_sync(0xffffffffu, p0, 2);
    p1 += __shfl_xor_sync(0xffffffffu, p1, 1);
    p1 += __shfl_xor_sync(0xffffffffu, p1, 2);
    if (tig == 0) {
        float blin0 = __ldg(blin);
        if (n0 < NN) out[n0] = p0 + blin0;
        if (n1 < NN) out[n1] = p1 + blin0;
    }
}

// ===========================================================================
extern "C" void kernel_launch(void* const* d_in, const int* in_sizes, int n_in,
                              void* d_out, int out_size)
{
    const float* x    = (const float*)d_in[0];
    const int*   ei   = (const int*)  d_in[1];
    const float* ew   = (const float*)d_in[2];
    const float* h    = (const float*)d_in[3];
    const float* c    = (const float*)d_in[4];
    const float* Wi   = (const float*)d_in[5];
    const float* bi   = (const float*)d_in[6];
    const float* thi  = (const float*)d_in[7];
    const float* cbi  = (const float*)d_in[8];
    const float* Wf   = (const float*)d_in[9];
    const float* bf   = (const float*)d_in[10];
    const float* thf  = (const float*)d_in[11];
    const float* cbf  = (const float*)d_in[12];
    const float* Wc   = (const float*)d_in[13];
    const float* bc   = (const float*)d_in[14];
    const float* thc  = (const float*)d_in[15];
    const float* cbc  = (const float*)d_in[16];
    const float* Wo   = (const float*)d_in[17];
    const float* bo   = (const float*)d_in[18];
    const float* tho  = (const float*)d_in[19];
    const float* cbo  = (const float*)d_in[20];
    const float* Wlin = (const float*)d_in[21];
    const float* blin = (const float*)d_in[22];
    float* out = (float*)d_out;

    cudaFuncSetAttribute(dense_kernel,
                         cudaFuncAttributeMaxDynamicSharedMemorySize, SM_TOTAL);

    prep_kernel<<<(NN * FOUT / 4 + 255) / 256, 256>>>(Wi, thi, Wf, thf, Wc, thc, Wo, tho);
    deg_kernel<<<(EE + 255) / 256, 256>>>(ei, ew);
    spmm4_kernel<<<(EE * 8 + 255) / 256, 256>>>(ei, ew, h);
    dense_kernel<<<NCTAS, 256, SM_TOTAL>>>(
        x, h, c,
        bi, cbi, bf, cbf, bc, cbc, bo, cbo,
        Wlin, blin, out);
}